// round 16
// baseline (speedup 1.0000x reference)
#include <cuda_runtime.h>
#include <math.h>

#define HH 192
#define WW 192
#define HW (HH*WW)
#define NBATCH 6
#define KC 400
#define MM 403
#define NCOL 405
#define SRIDE 416
#define LAMBDAV 100.0f
#define BIGV 1.0e8f
#define EPSV 1e-9f
#define STEPC (2.0f/191.0f)
#define HALF_LN2 0.34657359028f
#define NTH 512
#define SDS 68
#define BST 352                 // Bs strip stride (floats)

// smem float offsets
#define OFF_SDINV 4352
#define OFF_BS    4416
#define OFF_AS    (OFF_BS + 64 * BST)        // 26944
#define SMFLOATS  (OFF_AS + 4096)            // 31040 floats = 124160 B

// ---------------- device scratch ----------------
__device__ float g_A[NBATCH * MM * SRIDE];
__device__ float g_warp[NBATCH * 5 * HW];
__device__ float g_src[NBATCH * KC * 2];
__device__ float g_sol[NBATCH * MM * 2];
__device__ unsigned g_buildcnt[NBATCH];

__device__ __forceinline__ unsigned ldv(unsigned* p) { return *(volatile unsigned*)p; }

// ---------------- Stage 1: backward warp ----------------
__global__ void warp_kernel(const float* __restrict__ duv,
                            const float* __restrict__ uv,
                            float* __restrict__ outMask)
{
    int idx = blockIdx.x * blockDim.x + threadIdx.x;
    if (idx >= NBATCH * HW) return;
    int n = idx / HW;
    int p = idx - n * HW;

    float u = uv[idx * 2 + 0];
    float v = uv[idx * 2 + 1];
    float x = (u + 1.0f) * 0.5f * (float)(WW - 1);
    float y = (v + 1.0f) * 0.5f * (float)(HH - 1);
    float x0f = floorf(x), y0f = floorf(y);
    float wx = x - x0f, wy = y - y0f;
    int x0 = (int)x0f, y0 = (int)y0f;

    float w00 = (1.0f - wx) * (1.0f - wy);
    float w10 = wx * (1.0f - wy);
    float w01 = (1.0f - wx) * wy;
    float w11 = wx * wy;

    float acc0 = 0.f, acc1 = 0.f, acc2 = 0.f, acc3 = 0.f, acc4 = 0.f;

    const int dxs[4] = {0, 1, 0, 1};
    const int dys[4] = {0, 0, 1, 1};
    const float wts[4] = {w00, w10, w01, w11};

    #pragma unroll
    for (int c = 0; c < 4; ++c) {
        int xi = x0 + dxs[c];
        int yi = y0 + dys[c];
        if (xi >= 0 && xi < WW && yi >= 0 && yi < HH) {
            int q = yi * WW + xi;
            float dux = duv[q * 2 + 0];
            float duy = duv[q * 2 + 1];
            float val = (fabsf(dux) <= 1.0f && fabsf(duy) <= 1.0f) ? 1.0f : 0.0f;
            float gx = xi * STEPC - 1.0f;
            float gy = yi * STEPC - 1.0f;
            float w = wts[c];
            acc0 += gx * w;
            acc1 += gy * w;
            acc2 += (dux - gx) * val * w;
            acc3 += (duy - gy) * val * w;
            acc4 += val * w;
        }
    }

    float mk = (acc4 > 0.5f) ? 1.0f : 0.0f;
    float* Wp = g_warp + n * 5 * HW;
    Wp[0 * HW + p] = acc0;
    Wp[1 * HW + p] = acc1;
    Wp[2 * HW + p] = acc2;
    Wp[3 * HW + p] = acc3;
    Wp[4 * HW + p] = mk;
    outMask[idx] = mk;
}

__global__ void pad_reset_kernel()
{
    if (threadIdx.x < NBATCH) g_buildcnt[threadIdx.x] = 0;
}
__global__ void pad_empty_kernel() {}

// ---------------- L21 row solve (true U upper in sU + sdinv) ----------------
__device__ void l21_rows(float* A, int k0, int tr0, int nr,
                         const float* sU, const float* sdinv, int tid)
{
    if (tid >= nr) return;
    float* rowp = A + (tr0 + tid) * SRIDE + k0;
    #pragma unroll 1
    for (int jb = 0; jb < 8; ++jb) {
        int J0 = jb * 8;
        float x[8];
        {
            float4 v0 = *(const float4*)&rowp[J0];
            float4 v1 = *(const float4*)&rowp[J0 + 4];
            x[0]=v0.x; x[1]=v0.y; x[2]=v0.z; x[3]=v0.w;
            x[4]=v1.x; x[5]=v1.y; x[6]=v1.z; x[7]=v1.w;
        }
        for (int i = 0; i < J0; ++i) {
            float li = rowp[i];
            float4 u0 = *(const float4*)&sU[i * SDS + J0];
            float4 u1 = *(const float4*)&sU[i * SDS + J0 + 4];
            x[0] = fmaf(-li, u0.x, x[0]); x[1] = fmaf(-li, u0.y, x[1]);
            x[2] = fmaf(-li, u0.z, x[2]); x[3] = fmaf(-li, u0.w, x[3]);
            x[4] = fmaf(-li, u1.x, x[4]); x[5] = fmaf(-li, u1.y, x[5]);
            x[6] = fmaf(-li, u1.z, x[6]); x[7] = fmaf(-li, u1.w, x[7]);
        }
        #pragma unroll
        for (int i = 0; i < 8; ++i) {
            float xi = x[i] * sdinv[J0 + i];
            x[i] = xi;
            const float* urow = &sU[(J0 + i) * SDS + J0];
            #pragma unroll
            for (int q = 0; q < 8; ++q)
                if (q > i) x[q] = fmaf(-xi, urow[q], x[q]);
        }
        {
            float4 v0 = {x[0], x[1], x[2], x[3]};
            float4 v1 = {x[4], x[5], x[6], x[7]};
            *(float4*)&rowp[J0] = v0;
            *(float4*)&rowp[J0 + 4] = v1;
        }
    }
}

// ---------------- solver: build (144 CTAs) + 6 SOLO per-matrix LU ----------------
__global__ void __launch_bounds__(NTH, 1) solve_kernel()
{
    extern __shared__ float smdyn[];
    int cta = blockIdx.x;
    int tid = threadIdx.x;
    int lane = tid & 31;
    int wid = tid >> 5;

    // ===== build: 144 CTAs, 24 per matrix =====
    {
        int n = cta % NBATCH;
        int part = cta / NBATCH;
        float* s_sx = smdyn;
        float* s_sy = smdyn + KC;
        float* s_m  = smdyn + 2 * KC;
        float* s_dx = smdyn + 3 * KC;
        float* s_dy = smdyn + 4 * KC;

        const float* Wp = g_warp + n * 5 * HW;
        for (int k = tid; k < KC; k += NTH) {
            int a = k / 20, b = k - a * 20;
            int ii = __double2int_rn(a * (191.0 / 19.0));
            int jj = __double2int_rn(b * (191.0 / 19.0));
            int p = ii * WW + jj;
            float sx = Wp[p];
            float sy = Wp[HW + p];
            float m  = Wp[4 * HW + p];
            s_sx[k] = sx; s_sy[k] = sy; s_m[k] = m;
            s_dx[k] = jj * STEPC - 1.0f;
            s_dy[k] = ii * STEPC - 1.0f;
            if (part == 0) {
                g_src[(n * KC + k) * 2 + 0] = sx;
                g_src[(n * KC + k) * 2 + 1] = sy;
            }
        }
        __syncthreads();

        float* A = g_A + n * MM * SRIDE;
        int r0 = part * 17;
        int r1 = min(MM, r0 + 17);
        for (int i = r0; i < r1; ++i) {
            for (int j = tid; j < NCOL; j += NTH) {
                float vout;
                if (i < KC) {
                    if (j < KC) {
                        float dx = s_sx[i] - s_sx[j];
                        float dy = s_sy[i] - s_sy[j];
                        float r2 = dx * dx + dy * dy;
                        vout = 0.5f * r2 * __logf(r2 + EPSV);
                        if (i == j) vout += LAMBDAV + BIGV * (1.0f - s_m[i]);
                    } else if (j == 400) vout = 1.0f;
                    else if (j == 401) vout = s_sx[i];
                    else if (j == 402) vout = s_sy[i];
                    else if (j == 403) vout = s_dx[i];
                    else               vout = s_dy[i];
                } else {
                    if (j < KC) {
                        vout = (i == 400) ? 1.0f : ((i == 401) ? s_sx[j] : s_sy[j]);
                    } else {
                        vout = 0.0f;
                    }
                }
                A[i * SRIDE + j] = vout;
            }
        }
        __threadfence();
        __syncthreads();
        if (tid == 0) atomicAdd(&g_buildcnt[n], 1u);
    }
    if (cta >= NBATCH) return;
    __syncthreads();

    // ===== SOLO per-matrix LU: CTA n = cta, zero cross-CTA sync =====
    int n = cta;
    float* A = g_A + n * MM * SRIDE;
    float* sT    = smdyn;               // 64 x SDS
    float* sdinv = smdyn + OFF_SDINV;   // 64
    float* Bs    = smdyn + OFF_BS;      // 64 x BST (full trailing strip)
    float* As    = smdyn + OFF_AS;      // 64 x 64 (L21 tile)

    if (tid == 0) { while (ldv(&g_buildcnt[n]) < 24u) {} }
    __syncthreads();
    __threadfence();

    for (int k = 0; k < 7; ++k) {
        int k0 = 64 * k;

        if (k < 6) {
            // ---- load diag tile, blocked register fact (4 groups of 16) ----
            for (int idx2 = tid; idx2 < 4096; idx2 += NTH)
                sT[(idx2 >> 6) * SDS + (idx2 & 63)] = A[(k0 + (idx2 >> 6)) * SRIDE + k0 + (idx2 & 63)];
            __syncthreads();

            #pragma unroll 1
            for (int g = 0; g < 4; ++g) {
                int c0 = g * 16;
                if (wid == 0 && lane < 16) {
                    float x[16];
                    #pragma unroll
                    for (int q = 0; q < 16; ++q) x[q] = sT[(c0 + lane) * SDS + c0 + q];
                    #pragma unroll
                    for (int j = 0; j < 16; ++j) {
                        float piv[16];
                        #pragma unroll
                        for (int q = 0; q < 16; ++q)
                            piv[q] = __shfl_sync(0x0000FFFFu, x[q], j);
                        if (lane > j) {
                            float m = x[j] * __fdividef(1.0f, piv[j]);
                            x[j] = m;
                            #pragma unroll
                            for (int q = 0; q < 16; ++q)
                                if (q > j) x[q] = fmaf(-m, piv[q], x[q]);
                        }
                    }
                    #pragma unroll
                    for (int q = 0; q < 16; ++q) sT[(c0 + lane) * SDS + c0 + q] = x[q];
                }
                __syncthreads();

                int ntrail = 64 - (c0 + 16);
                if (tid < ntrail) {                       // sub-U12 col solve
                    int c = c0 + 16 + tid;
                    float x[16];
                    #pragma unroll
                    for (int r = 0; r < 16; ++r) x[r] = sT[(c0 + r) * SDS + c];
                    #pragma unroll
                    for (int i = 0; i < 16; ++i) {
                        float xi = x[i];
                        #pragma unroll
                        for (int r = 0; r < 16; ++r)
                            if (r > i) x[r] = fmaf(-sT[(c0 + r) * SDS + c0 + i], xi, x[r]);
                    }
                    #pragma unroll
                    for (int r = 1; r < 16; ++r) sT[(c0 + r) * SDS + c] = x[r];
                } else if (tid >= 64 && tid < 64 + ntrail) {   // sub-L21 row solve
                    int r = c0 + 16 + (tid - 64);
                    float x[16];
                    #pragma unroll
                    for (int q = 0; q < 16; ++q) x[q] = sT[r * SDS + c0 + q];
                    #pragma unroll
                    for (int i = 0; i < 16; ++i) {
                        float xi = x[i] * __fdividef(1.0f, sT[(c0 + i) * SDS + c0 + i]);
                        x[i] = xi;
                        #pragma unroll
                        for (int q = 0; q < 16; ++q)
                            if (q > i) x[q] = fmaf(-xi, sT[(c0 + i) * SDS + c0 + q], x[q]);
                    }
                    #pragma unroll
                    for (int q = 0; q < 16; ++q) sT[r * SDS + c0 + q] = x[q];
                }
                __syncthreads();

                if (ntrail > 0) {                         // rank-16 trailing update
                    int tot = ntrail * ntrail;
                    for (int idx2 = tid; idx2 < tot; idx2 += NTH) {
                        int r = c0 + 16 + idx2 / ntrail;
                        int c = c0 + 16 + idx2 % ntrail;
                        float acc = sT[r * SDS + c];
                        #pragma unroll
                        for (int i = 0; i < 16; ++i)
                            acc = fmaf(-sT[r * SDS + c0 + i], sT[(c0 + i) * SDS + c], acc);
                        sT[r * SDS + c] = acc;
                    }
                    __syncthreads();
                }
            }
            if (tid < 64) sdinv[tid] = __fdividef(1.0f, sT[tid * SDS + tid]);
            for (int idx2 = tid; idx2 < 4096; idx2 += NTH)
                A[(k0 + (idx2 >> 6)) * SRIDE + k0 + (idx2 & 63)] = sT[(idx2 >> 6) * SDS + (idx2 & 63)];
            __syncthreads();
        } else {
            // ---- final 19x21 fact (includes RHS cols 403,404) ----
            int nbr = 19, nbc = 21;
            for (int idx2 = tid; idx2 < nbr * nbc; idx2 += NTH) {
                int rr = idx2 / nbc, cc = idx2 - rr * nbc;
                sT[rr * SDS + cc] = A[(k0 + rr) * SRIDE + k0 + cc];
            }
            __syncthreads();
            int r = tid & 63, cg = tid >> 6;
            for (int j = 0; j < nbr - 1; ++j) {
                float pinv = __fdividef(1.0f, sT[j * SDS + j]);
                if (r > j && r < nbr && cg == 0)
                    sT[r * SDS + j] = sT[r * SDS + j] * pinv;
                __syncthreads();
                if (r > j && r < nbr) {
                    float m = sT[r * SDS + j];
                    for (int c = j + 1 + cg; c < nbc; c += 8)
                        sT[r * SDS + c] = fmaf(-m, sT[j * SDS + c], sT[r * SDS + c]);
                }
                __syncthreads();
            }
            for (int idx2 = tid; idx2 < nbr * nbc; idx2 += NTH) {
                int rr = idx2 / nbc, cc = idx2 - rr * nbc;
                A[(k0 + rr) * SRIDE + k0 + cc] = sT[rr * SDS + cc];
            }
            __syncthreads();
            break;
        }

        int col0 = k0 + 64;
        int wtot = NCOL - col0;          // up to 341

        // ---- load full trailing strip into Bs ----
        for (int idx2 = tid; idx2 < 64 * BST; idx2 += NTH) {
            int r = idx2 / BST, c = idx2 - r * BST;
            Bs[idx2] = (c < wtot) ? A[(k0 + r) * SRIDE + col0 + c] : 0.0f;
        }
        __syncthreads();

        // ---- full-width trisolve vs unit-lower L in sT (16-row blocking) ----
        #pragma unroll 1
        for (int ib = 0; ib < 4; ++ib) {
            int base = ib * 16;
            if (tid < wtot) {
                int c = tid;
                float x[16];
                #pragma unroll
                for (int rr2 = 0; rr2 < 16; ++rr2) x[rr2] = Bs[(base + rr2) * BST + c];
                #pragma unroll
                for (int i = 0; i < 16; ++i) {
                    float xi = x[i];
                    #pragma unroll
                    for (int rr2 = 0; rr2 < 16; ++rr2)
                        if (rr2 > i) x[rr2] = fmaf(-sT[(base + rr2) * SDS + base + i], xi, x[rr2]);
                }
                #pragma unroll
                for (int rr2 = 1; rr2 < 16; ++rr2) Bs[(base + rr2) * BST + c] = x[rr2];
            }
            __syncthreads();
            if (base + 16 < 64) {
                for (int rr2 = base + 16; rr2 < 64; ++rr2) {
                    for (int c = tid; c < wtot; c += NTH) {
                        float acc = Bs[rr2 * BST + c];
                        #pragma unroll
                        for (int i = 0; i < 16; ++i)
                            acc = fmaf(-sT[rr2 * SDS + base + i], Bs[(base + i) * BST + c], acc);
                        Bs[rr2 * BST + c] = acc;
                    }
                }
            }
            __syncthreads();
        }

        // ---- store U12 strip back ----
        for (int idx2 = tid; idx2 < 64 * BST; idx2 += NTH) {
            int r = idx2 / BST, c = idx2 - r * BST;
            if (c < wtot) A[(k0 + r) * SRIDE + col0 + c] = Bs[idx2];
        }
        __syncthreads();

        // ---- L21 for ALL trailing rows at once (nr <= 339 <= NTH) ----
        {
            int nr = MM - col0;
            l21_rows(A, k0, col0, nr, sT, sdinv, tid);
        }
        __syncthreads();

        // ---- GEMM: trailing -= L21 * U12, 4r x 8c register tiles ----
        {
            int tg = tid >> 5;           // 16 row groups (4 rows each)
            int cg2 = tid & 31;          // 32 col groups (8 cols each)
            int rb = tg * 4;
            for (int row0 = col0; row0 < MM; row0 += 64) {
                int nrows = MM - row0; if (nrows > 64) nrows = 64;
                for (int idx2 = tid; idx2 < 4096; idx2 += NTH) {
                    int r = idx2 >> 6, c = idx2 & 63;
                    As[idx2] = (r < nrows) ? A[(row0 + r) * SRIDE + k0 + c] : 0.0f;
                }
                __syncthreads();

                for (int pass = 0; pass * 256 < wtot; ++pass) {
                    int cb = pass * 256 + cg2 * 8;
                    if (cb < wtot) {
                        float acc[4][8];
                        #pragma unroll
                        for (int i = 0; i < 4; ++i)
                            #pragma unroll
                            for (int q = 0; q < 8; ++q) acc[i][q] = 0.0f;

                        for (int kk = 0; kk < 64; ++kk) {
                            float4 b0 = *(const float4*)&Bs[kk * BST + cb];
                            float4 b1 = *(const float4*)&Bs[kk * BST + cb + 4];
                            float a0 = As[(rb + 0) * 64 + kk];
                            float a1 = As[(rb + 1) * 64 + kk];
                            float a2 = As[(rb + 2) * 64 + kk];
                            float a3 = As[(rb + 3) * 64 + kk];
                            acc[0][0]=fmaf(a0,b0.x,acc[0][0]); acc[0][1]=fmaf(a0,b0.y,acc[0][1]);
                            acc[0][2]=fmaf(a0,b0.z,acc[0][2]); acc[0][3]=fmaf(a0,b0.w,acc[0][3]);
                            acc[0][4]=fmaf(a0,b1.x,acc[0][4]); acc[0][5]=fmaf(a0,b1.y,acc[0][5]);
                            acc[0][6]=fmaf(a0,b1.z,acc[0][6]); acc[0][7]=fmaf(a0,b1.w,acc[0][7]);
                            acc[1][0]=fmaf(a1,b0.x,acc[1][0]); acc[1][1]=fmaf(a1,b0.y,acc[1][1]);
                            acc[1][2]=fmaf(a1,b0.z,acc[1][2]); acc[1][3]=fmaf(a1,b0.w,acc[1][3]);
                            acc[1][4]=fmaf(a1,b1.x,acc[1][4]); acc[1][5]=fmaf(a1,b1.y,acc[1][5]);
                            acc[1][6]=fmaf(a1,b1.z,acc[1][6]); acc[1][7]=fmaf(a1,b1.w,acc[1][7]);
                            acc[2][0]=fmaf(a2,b0.x,acc[2][0]); acc[2][1]=fmaf(a2,b0.y,acc[2][1]);
                            acc[2][2]=fmaf(a2,b0.z,acc[2][2]); acc[2][3]=fmaf(a2,b0.w,acc[2][3]);
                            acc[2][4]=fmaf(a2,b1.x,acc[2][4]); acc[2][5]=fmaf(a2,b1.y,acc[2][5]);
                            acc[2][6]=fmaf(a2,b1.z,acc[2][6]); acc[2][7]=fmaf(a2,b1.w,acc[2][7]);
                            acc[3][0]=fmaf(a3,b0.x,acc[3][0]); acc[3][1]=fmaf(a3,b0.y,acc[3][1]);
                            acc[3][2]=fmaf(a3,b0.z,acc[3][2]); acc[3][3]=fmaf(a3,b0.w,acc[3][3]);
                            acc[3][4]=fmaf(a3,b1.x,acc[3][4]); acc[3][5]=fmaf(a3,b1.y,acc[3][5]);
                            acc[3][6]=fmaf(a3,b1.z,acc[3][6]); acc[3][7]=fmaf(a3,b1.w,acc[3][7]);
                        }

                        bool full8 = (cb + 8 <= wtot);
                        #pragma unroll
                        for (int i = 0; i < 4; ++i) {
                            int r = rb + i;
                            if (r < nrows) {
                                float* dst = &A[(row0 + r) * SRIDE + col0 + cb];
                                if (full8) {
                                    float4 v0 = *(float4*)dst;
                                    float4 v1 = *(float4*)(dst + 4);
                                    v0.x -= acc[i][0]; v0.y -= acc[i][1];
                                    v0.z -= acc[i][2]; v0.w -= acc[i][3];
                                    v1.x -= acc[i][4]; v1.y -= acc[i][5];
                                    v1.z -= acc[i][6]; v1.w -= acc[i][7];
                                    *(float4*)dst = v0;
                                    *(float4*)(dst + 4) = v1;
                                } else {
                                    #pragma unroll
                                    for (int q = 0; q < 8; ++q)
                                        if (cb + q < wtot) dst[q] -= acc[i][q];
                                }
                            }
                        }
                    }
                }
                __syncthreads();
            }
        }
    }

    // ===== back-substitution =====
    {
        float* sB  = smdyn;              // 64x65
        float* x0s = smdyn + OFF_BS;     // reuse Bs region
        float* x1s = x0s + MM;

        __syncthreads();
        for (int j = tid; j < MM; j += NTH) {
            x0s[j] = A[j * SRIDE + 403];
            x1s[j] = A[j * SRIDE + 404];
        }
        __syncthreads();

        for (int b = 6; b >= 0; --b) {
            int bk0 = b * 64;
            int bnb = (MM - bk0 < 64) ? (MM - bk0) : 64;

            for (int idx2 = tid; idx2 < bnb * bnb; idx2 += NTH) {
                int r = idx2 / bnb, cc = idx2 - r * bnb;
                sB[r * 65 + cc] = A[(bk0 + r) * SRIDE + bk0 + cc];
            }
            __syncthreads();

            if (wid == 0) {
                for (int k = bnb - 1; k >= 0; --k) {
                    float s0 = 0.f, s1 = 0.f;
                    for (int j = k + 1 + lane; j < bnb; j += 32) {
                        float u = sB[k * 65 + j];
                        s0 = fmaf(u, x0s[bk0 + j], s0);
                        s1 = fmaf(u, x1s[bk0 + j], s1);
                    }
                    #pragma unroll
                    for (int off = 16; off > 0; off >>= 1) {
                        s0 += __shfl_down_sync(0xffffffffu, s0, off);
                        s1 += __shfl_down_sync(0xffffffffu, s1, off);
                    }
                    if (lane == 0) {
                        float d = 1.0f / sB[k * 65 + k];
                        x0s[bk0 + k] = (x0s[bk0 + k] - s0) * d;
                        x1s[bk0 + k] = (x1s[bk0 + k] - s1) * d;
                    }
                    __syncwarp();
                }
            }
            __syncthreads();

            for (int r = tid; r < bk0; r += NTH) {
                float s0 = 0.f, s1 = 0.f;
                const float* Ur = A + r * SRIDE + bk0;
                #pragma unroll 8
                for (int j = 0; j < bnb; ++j) {
                    float u = Ur[j];
                    s0 = fmaf(u, x0s[bk0 + j], s0);
                    s1 = fmaf(u, x1s[bk0 + j], s1);
                }
                x0s[r] -= s0;
                x1s[r] -= s1;
            }
            __syncthreads();
        }

        for (int j = tid; j < MM; j += NTH) {
            g_sol[(n * MM + j) * 2 + 0] = x0s[j];
            g_sol[(n * MM + j) * 2 + 1] = x1s[j];
        }
    }
}

// ---------------- Stage 4: TPS evaluation + Jacobian + output ----------------
__global__ void __launch_bounds__(256) eval_kernel(float* __restrict__ outDef)
{
    int n = blockIdx.y;
    int p = blockIdx.x * blockDim.x + threadIdx.x;
    int tid = threadIdx.x;

    __shared__ float4 s_sw[KC];
    __shared__ float s_aff[6];

    for (int k = tid; k < KC; k += blockDim.x) {
        float4 t;
        t.x = g_src[(n * KC + k) * 2 + 0];
        t.y = g_src[(n * KC + k) * 2 + 1];
        t.z = g_sol[(n * MM + k) * 2 + 0] * HALF_LN2;
        t.w = g_sol[(n * MM + k) * 2 + 1] * HALF_LN2;
        s_sw[k] = t;
    }
    if (tid < 6) s_aff[tid] = g_sol[(n * MM + 400) * 2 + tid];
    __syncthreads();

    const float* Wp = g_warp + n * 5 * HW;
    float q0x = Wp[p];
    float q0y = Wp[HW + p];
    float dlx = Wp[2 * HW + p];
    float dly = Wp[3 * HW + p];
    float mk  = Wp[4 * HW + p];

    float a0x = 0.f, a0y = 0.f, a1x = 0.f, a1y = 0.f, a2x = 0.f, a2y = 0.f;

    #pragma unroll 4
    for (int k = 0; k < KC; ++k) {
        float4 s = s_sw[k];
        float d0x = q0x - s.x;
        float d0y = q0y - s.y;
        float e0x = fmaf(2.0f, d0x, STEPC);
        float e0y = fmaf(2.0f, d0y, STEPC);
        float r0 = fmaf(d0x, d0x, d0y * d0y) + EPSV;
        float r1 = fmaf(STEPC, e0x, r0);
        float r2 = fmaf(STEPC, e0y, r0);
        float u0 = r0 * __log2f(r0);
        float u1 = r1 * __log2f(r1);
        float u2 = r2 * __log2f(r2);
        a0x = fmaf(u0, s.z, a0x);  a0y = fmaf(u0, s.w, a0y);
        a1x = fmaf(u1, s.z, a1x);  a1y = fmaf(u1, s.w, a1y);
        a2x = fmaf(u2, s.z, a2x);  a2y = fmaf(u2, s.w, a2y);
    }

    float q1x = q0x + STEPC;
    float q2y = q0y + STEPC;
    float c0x = a0x + s_aff[0] + s_aff[2] * q0x + s_aff[4] * q0y;
    float c0y = a0y + s_aff[1] + s_aff[3] * q0x + s_aff[5] * q0y;
    float c1x = a1x + s_aff[0] + s_aff[2] * q1x + s_aff[4] * q0y;
    float c1y = a1y + s_aff[1] + s_aff[3] * q1x + s_aff[5] * q0y;
    float c2x = a2x + s_aff[0] + s_aff[2] * q0x + s_aff[4] * q2y;
    float c2y = a2y + s_aff[1] + s_aff[3] * q0x + s_aff[5] * q2y;

    float ja = (c1x - c0x) / STEPC;
    float jb = (c1y - c0y) / STEPC;
    float jc = (c2x - c0x) / STEPC;
    float jd = (c2y - c0y) / STEPC;

    float dnx = ja * dlx + jc * dly;
    float dny = jb * dlx + jd * dly;

    int i = p / WW;
    int j = p - i * WW;
    float gx = j * STEPC - 1.0f;
    float gy = i * STEPC - 1.0f;
    float dfx = (gx + dnx) * mk - 2.0f * (1.0f - mk);
    float dfy = (gy + dny) * mk - 2.0f * (1.0f - mk);

    outDef[(n * HW + p) * 2 + 0] = dfx;
    outDef[(n * HW + p) * 2 + 1] = dfy;
}

// ---------------- launch ----------------
extern "C" void kernel_launch(void* const* d_in, const int* in_sizes, int n_in,
                              void* d_out, int out_size)
{
    const float* a0 = (const float*)d_in[0];
    const float* a1 = (const float*)d_in[1];
    const float* duv;
    const float* uv;
    if (in_sizes[0] == 2 * HW) { duv = a0; uv = a1; }
    else                        { duv = a1; uv = a0; }

    float* out = (float*)d_out;
    float* outDef  = out;
    float* outMask = out + NBATCH * HW * 2;

    const int SMBYTES = SMFLOATS * (int)sizeof(float);   // ~124 KB dynamic
    cudaFuncSetAttribute(solve_kernel,
                         cudaFuncAttributeMaxDynamicSharedMemorySize, SMBYTES);

    warp_kernel<<<(NBATCH * HW + 255) / 256, 256>>>(duv, uv, outMask);
    pad_reset_kernel<<<1, 32>>>();
    pad_empty_kernel<<<1, 32>>>();
    solve_kernel<<<144, NTH, SMBYTES>>>();
    eval_kernel<<<dim3(HW / 256, NBATCH), 256>>>(outDef);
}

// round 17
// speedup vs baseline: 1.8822x; 1.8822x over previous
#include <cuda_runtime.h>
#include <math.h>

#define HH 192
#define WW 192
#define HW (HH*WW)
#define NBATCH 6
#define KC 400
#define MM 403
#define NCOL 405
#define SRIDE 416
#define LAMBDAV 100.0f
#define BIGV 1.0e8f
#define EPSV 1e-9f
#define STEPC (2.0f/191.0f)
#define HALF_LN2 0.34657359028f
#define NTH 512
#define SDS 68

__device__ float g_A[NBATCH * MM * SRIDE];
__device__ float g_warp[NBATCH * 5 * HW];
__device__ float g_src[NBATCH * KC * 2];
__device__ float g_sol[NBATCH * MM * 2];
__device__ unsigned g_buildcnt[NBATCH];
__device__ unsigned g_factpub[NBATCH];
__device__ unsigned g_uready[NBATCH];
__device__ unsigned g_l21pan[NBATCH];
__device__ unsigned g_l21par[NBATCH * 3];
__device__ unsigned g_progh[NBATCH * 16];
__device__ unsigned g_ft[NBATCH * 16];
__device__ unsigned g_tdone[NBATCH * 8];
__device__ unsigned g_ust[NBATCH * 8];
__device__ unsigned g_solflag[NBATCH];

__device__ __forceinline__ unsigned ldv(unsigned* p) { return *(volatile unsigned*)p; }

__global__ void warp_kernel(const float* __restrict__ duv,
                            const float* __restrict__ uv,
                            float* __restrict__ outMask)
{
    if (blockIdx.x == 0) {
        if (threadIdx.x < NBATCH) {
            g_buildcnt[threadIdx.x] = 0;
            g_factpub[threadIdx.x] = 0;
            g_uready[threadIdx.x] = 0;
            g_l21pan[threadIdx.x] = 0;
            g_solflag[threadIdx.x] = 0;
        }
        if (threadIdx.x < NBATCH * 3) g_l21par[threadIdx.x] = 0;
        if (threadIdx.x < NBATCH * 8) {
            g_tdone[threadIdx.x] = 0;
            g_ust[threadIdx.x] = 0;
        }
        if (threadIdx.x < NBATCH * 16) {
            g_progh[threadIdx.x] = 0;
            g_ft[threadIdx.x] = 0;
        }
    }

    int idx = blockIdx.x * blockDim.x + threadIdx.x;
    if (idx >= NBATCH * HW) return;
    int n = idx / HW;
    int p = idx - n * HW;

    float u = uv[idx * 2 + 0];
    float v = uv[idx * 2 + 1];
    float x = (u + 1.0f) * 0.5f * (float)(WW - 1);
    float y = (v + 1.0f) * 0.5f * (float)(HH - 1);
    float x0f = floorf(x), y0f = floorf(y);
    float wx = x - x0f, wy = y - y0f;
    int x0 = (int)x0f, y0 = (int)y0f;

    float w00 = (1.0f - wx) * (1.0f - wy);
    float w10 = wx * (1.0f - wy);
    float w01 = (1.0f - wx) * wy;
    float w11 = wx * wy;

    float acc0 = 0.f, acc1 = 0.f, acc2 = 0.f, acc3 = 0.f, acc4 = 0.f;

    const int dxs[4] = {0, 1, 0, 1};
    const int dys[4] = {0, 0, 1, 1};
    const float wts[4] = {w00, w10, w01, w11};

    #pragma unroll
    for (int c = 0; c < 4; ++c) {
        int xi = x0 + dxs[c];
        int yi = y0 + dys[c];
        if (xi >= 0 && xi < WW && yi >= 0 && yi < HH) {
            int q = yi * WW + xi;
            float dux = duv[q * 2 + 0];
            float duy = duv[q * 2 + 1];
            float val = (fabsf(dux) <= 1.0f && fabsf(duy) <= 1.0f) ? 1.0f : 0.0f;
            float gx = xi * STEPC - 1.0f;
            float gy = yi * STEPC - 1.0f;
            float w = wts[c];
            acc0 += gx * w;
            acc1 += gy * w;
            acc2 += (dux - gx) * val * w;
            acc3 += (duy - gy) * val * w;
            acc4 += val * w;
        }
    }

    float mk = (acc4 > 0.5f) ? 1.0f : 0.0f;
    float* Wp = g_warp + n * 5 * HW;
    Wp[0 * HW + p] = acc0;
    Wp[1 * HW + p] = acc1;
    Wp[2 * HW + p] = acc2;
    Wp[3 * HW + p] = acc3;
    Wp[4 * HW + p] = mk;
    outMask[idx] = mk;
}

#define ACC4(acc, aa, bb) \
    acc.x = fmaf(aa, bb.x, acc.x); acc.y = fmaf(aa, bb.y, acc.y); \
    acc.z = fmaf(aa, bb.z, acc.z); acc.w = fmaf(aa, bb.w, acc.w);

__device__ void gemm_tiles(float* A, int k0, int col0, int w,
                           int rowStart, int rowStride,
                           const float* Bs, float* As, int tid)
{
    int c4 = (tid & 15) * 4;
    int r0 = (tid >> 4) * 2;
    int r1 = r0 + 1;
    for (int row0 = rowStart; row0 < MM; row0 += rowStride) {
        int nrows = MM - row0; if (nrows > 64) nrows = 64;
        for (int idx = tid; idx < 4096; idx += NTH) {
            int r = idx >> 6, c = idx & 63;
            As[idx] = (r < nrows) ? A[(row0 + r) * SRIDE + k0 + c] : 0.0f;
        }
        __syncthreads();

        float4 acc0 = {0.f,0.f,0.f,0.f};
        float4 acc1 = {0.f,0.f,0.f,0.f};
        #pragma unroll
        for (int kk4 = 0; kk4 < 16; ++kk4) {
            float4 a0 = *(const float4*)&As[r0 * 64 + kk4 * 4];
            float4 a1 = *(const float4*)&As[r1 * 64 + kk4 * 4];
            const float* bb = &Bs[(kk4 * 4) * 64 + c4];
            float4 b0 = *(const float4*)(bb);
            float4 b1 = *(const float4*)(bb + 64);
            float4 b2 = *(const float4*)(bb + 128);
            float4 b3 = *(const float4*)(bb + 192);
            ACC4(acc0, a0.x, b0) ACC4(acc0, a0.y, b1) ACC4(acc0, a0.z, b2) ACC4(acc0, a0.w, b3)
            ACC4(acc1, a1.x, b0) ACC4(acc1, a1.y, b1) ACC4(acc1, a1.z, b2) ACC4(acc1, a1.w, b3)
        }

        if (w == 64) {
            if (r0 < nrows) {
                float4 v = *(float4*)&A[(row0 + r0) * SRIDE + col0 + c4];
                v.x -= acc0.x; v.y -= acc0.y; v.z -= acc0.z; v.w -= acc0.w;
                *(float4*)&A[(row0 + r0) * SRIDE + col0 + c4] = v;
            }
            if (r1 < nrows) {
                float4 v = *(float4*)&A[(row0 + r1) * SRIDE + col0 + c4];
                v.x -= acc1.x; v.y -= acc1.y; v.z -= acc1.z; v.w -= acc1.w;
                *(float4*)&A[(row0 + r1) * SRIDE + col0 + c4] = v;
            }
        } else {
            float a0a[4] = {acc0.x, acc0.y, acc0.z, acc0.w};
            float a1a[4] = {acc1.x, acc1.y, acc1.z, acc1.w};
            #pragma unroll
            for (int q = 0; q < 4; ++q) {
                int c = c4 + q;
                if (c < w) {
                    if (r0 < nrows) A[(row0 + r0) * SRIDE + col0 + c] -= a0a[q];
                    if (r1 < nrows) A[(row0 + r1) * SRIDE + col0 + c] -= a1a[q];
                }
            }
        }
        __syncthreads();
    }
}

__device__ void l21_rows(float* A, int k0, int tr0, int nr,
                         const float* sU, const float* sdinv,
                         float* AsOut, int tid)
{
    if (tid >= nr) return;
    float* rowp = A + (tr0 + tid) * SRIDE + k0;
    #pragma unroll 1
    for (int jb = 0; jb < 8; ++jb) {
        int J0 = jb * 8;
        float x[8];
        {
            float4 v0 = *(const float4*)&rowp[J0];
            float4 v1 = *(const float4*)&rowp[J0 + 4];
            x[0]=v0.x; x[1]=v0.y; x[2]=v0.z; x[3]=v0.w;
            x[4]=v1.x; x[5]=v1.y; x[6]=v1.z; x[7]=v1.w;
        }
        for (int i = 0; i < J0; ++i) {
            float li = rowp[i];
            float4 u0 = *(const float4*)&sU[i * SDS + J0];
            float4 u1 = *(const float4*)&sU[i * SDS + J0 + 4];
            x[0] = fmaf(-li, u0.x, x[0]); x[1] = fmaf(-li, u0.y, x[1]);
            x[2] = fmaf(-li, u0.z, x[2]); x[3] = fmaf(-li, u0.w, x[3]);
            x[4] = fmaf(-li, u1.x, x[4]); x[5] = fmaf(-li, u1.y, x[5]);
            x[6] = fmaf(-li, u1.z, x[6]); x[7] = fmaf(-li, u1.w, x[7]);
        }
        #pragma unroll
        for (int i = 0; i < 8; ++i) {
            float xi = x[i] * sdinv[J0 + i];
            x[i] = xi;
            const float* urow = &sU[(J0 + i) * SDS + J0];
            #pragma unroll
            for (int q = 0; q < 8; ++q)
                if (q > i) x[q] = fmaf(-xi, urow[q], x[q]);
        }
        {
            float4 v0 = {x[0], x[1], x[2], x[3]};
            float4 v1 = {x[4], x[5], x[6], x[7]};
            *(float4*)&rowp[J0] = v0;
            *(float4*)&rowp[J0 + 4] = v1;
        }
        if (AsOut) {
            #pragma unroll
            for (int q = 0; q < 8; ++q) AsOut[tid * 64 + J0 + q] = x[q];
        }
    }
}

__device__ void trisolve_block(const float* L, int ls, float* Bs, int tid)
{
    #pragma unroll
    for (int ib = 0; ib < 4; ++ib) {
        int base = ib * 16;
        if (tid < 64) {
            int c = tid;
            float x[16];
            #pragma unroll
            for (int r = 0; r < 16; ++r) x[r] = Bs[(base + r) * 64 + c];
            #pragma unroll
            for (int i = 0; i < 16; ++i) {
                float xi = x[i];
                #pragma unroll
                for (int r = 0; r < 16; ++r)
                    if (r > i) x[r] = fmaf(-L[(base + r) * ls + base + i], xi, x[r]);
            }
            #pragma unroll
            for (int r = 1; r < 16; ++r) Bs[(base + r) * 64 + c] = x[r];
        }
        __syncthreads();
        if (base + 16 < 64) {
            int c = tid & 63;
            int g = tid >> 6;
            for (int jj = base + 16 + g; jj < 64; jj += 8) {
                float acc = Bs[jj * 64 + c];
                #pragma unroll
                for (int i = 0; i < 16; ++i)
                    acc = fmaf(-L[jj * ls + base + i], Bs[(base + i) * 64 + c], acc);
                Bs[jj * 64 + c] = acc;
            }
        }
        __syncthreads();
    }
}

__global__ void __launch_bounds__(NTH, 1) solve_kernel(float* __restrict__ outDef)
{
    extern __shared__ float smdyn[];
    int cta = blockIdx.x;
    int tid = threadIdx.x;
    int lane = tid & 31;
    int wid = tid >> 5;

    // ===== build =====
    {
        int n = cta % NBATCH;
        int part = cta / NBATCH;
        float* s_sx = smdyn;
        float* s_sy = smdyn + KC;
        float* s_m  = smdyn + 2 * KC;
        float* s_dx = smdyn + 3 * KC;
        float* s_dy = smdyn + 4 * KC;

        const float* Wp = g_warp + n * 5 * HW;
        for (int k = tid; k < KC; k += NTH) {
            int a = k / 20, b = k - a * 20;
            int ii = __double2int_rn(a * (191.0 / 19.0));
            int jj = __double2int_rn(b * (191.0 / 19.0));
            int p = ii * WW + jj;
            float sx = Wp[p];
            float sy = Wp[HW + p];
            float m  = Wp[4 * HW + p];
            s_sx[k] = sx; s_sy[k] = sy; s_m[k] = m;
            s_dx[k] = jj * STEPC - 1.0f;
            s_dy[k] = ii * STEPC - 1.0f;
            if (part == 0) {
                g_src[(n * KC + k) * 2 + 0] = sx;
                g_src[(n * KC + k) * 2 + 1] = sy;
            }
        }
        __syncthreads();

        float* A = g_A + n * MM * SRIDE;
        int r0 = part * 17;
        int r1 = min(MM, r0 + 17);
        for (int i = r0; i < r1; ++i) {
            for (int j = tid; j < NCOL; j += NTH) {
                float vout;
                if (i < KC) {
                    if (j < KC) {
                        float dx = s_sx[i] - s_sx[j];
                        float dy = s_sy[i] - s_sy[j];
                        float r2 = dx * dx + dy * dy;
                        vout = 0.5f * r2 * __logf(r2 + EPSV);
                        if (i == j) vout += LAMBDAV + BIGV * (1.0f - s_m[i]);
                    } else if (j == 400) vout = 1.0f;
                    else if (j == 401) vout = s_sx[i];
                    else if (j == 402) vout = s_sy[i];
                    else if (j == 403) vout = s_dx[i];
                    else               vout = s_dy[i];
                } else {
                    if (j < KC) {
                        vout = (i == 400) ? 1.0f : ((i == 401) ? s_sx[j] : s_sy[j]);
                    } else {
                        vout = 0.0f;
                    }
                }
                A[i * SRIDE + j] = vout;
            }
        }
        __threadfence();
        __syncthreads();
        if (tid == 0) atomicAdd(&g_buildcnt[n], 1u);
    }
    __syncthreads();

    if (cta >= 24 && cta < 84) {
        int idx = cta - 24;
        int n = idx / 10;
        int rem = idx - n * 10;
        int B = 2 + rem / 2;
        int h = rem & 1;
        float* A = g_A + n * MM * SRIDE;
        float* sL = smdyn;
        float* Bs = smdyn + 4096;
        float* As = smdyn + 8192;

        for (int j = 0; j <= B - 2; ++j) {
            int k0 = 64 * j;
            int col0 = 64 * B;
            int w = NCOL - col0; if (w > 64) w = 64;

            if (h == 0) {
                if (tid == 0) {
                    while (ldv(&g_factpub[n]) < (unsigned)(j + 1)) {}
                    if (j >= 1) { while (ldv(&g_ft[n * 16 + B * 2 + 1]) < (unsigned)(j - 1)) {} }
                }
                __syncthreads();
                __threadfence();

                for (int idx2 = tid; idx2 < 4096; idx2 += NTH) {
                    int r = idx2 >> 6, c = idx2 & 63;
                    sL[idx2] = A[(k0 + r) * SRIDE + k0 + c];
                    Bs[idx2] = (c < w) ? A[(k0 + r) * SRIDE + col0 + c] : 0.0f;
                }
                __syncthreads();
                trisolve_block(sL, 64, Bs, tid);
                for (int idx2 = tid; idx2 < 4096; idx2 += NTH) {
                    int r = idx2 >> 6, c = idx2 & 63;
                    if (c < w) A[(k0 + r) * SRIDE + col0 + c] = Bs[idx2];
                }
                __threadfence();
                __syncthreads();
                if (tid == 0) atomicExch(&g_ust[n * 8 + B], (unsigned)(j + 1));

                if (tid == 0) {
                    while (ldv(&g_l21pan[n]) < (unsigned)(j + 1)) {}
                    if (j >= 1) { while (ldv(&g_ft[n * 16 + B * 2 + 1]) < (unsigned)j) {} }
                }
                __syncthreads();
                __threadfence();
                gemm_tiles(A, k0, col0, w, k0 + 64, 1 << 20, Bs, As, tid);
                __threadfence();
                __syncthreads();
                if (tid == 0) atomicExch(&g_ft[n * 16 + B * 2 + 0], (unsigned)(j + 1));

                if (tid == 0) {
                    while (ldv(&g_progh[n * 16 + B * 2 + 1]) < (unsigned)j) {}
                    while (ldv(&g_l21par[n * 3 + 0]) < (unsigned)(j + 1)) {}
                    while (ldv(&g_l21par[n * 3 + 1]) < (unsigned)(j + 1)) {}
                    while (ldv(&g_l21par[n * 3 + 2]) < (unsigned)(j + 1)) {}
                }
                __syncthreads();
                __threadfence();
                gemm_tiles(A, k0, col0, w, k0 + 64 + 128, 128, Bs, As, tid);
                __threadfence();
                __syncthreads();
                if (tid == 0) atomicExch(&g_progh[n * 16 + B * 2 + 0], (unsigned)(j + 1));
            } else {
                if (tid == 0) {
                    while (ldv(&g_ust[n * 8 + B]) < (unsigned)(j + 1)) {}
                    if (j >= 1) { while (ldv(&g_progh[n * 16 + B * 2 + 0]) < (unsigned)j) {} }
                    while (ldv(&g_l21par[n * 3 + 0]) < (unsigned)(j + 1)) {}
                    while (ldv(&g_l21par[n * 3 + 1]) < (unsigned)(j + 1)) {}
                    while (ldv(&g_l21par[n * 3 + 2]) < (unsigned)(j + 1)) {}
                }
                __syncthreads();
                __threadfence();

                for (int idx2 = tid; idx2 < 4096; idx2 += NTH) {
                    int r = idx2 >> 6, c = idx2 & 63;
                    Bs[idx2] = (c < w) ? A[(k0 + r) * SRIDE + col0 + c] : 0.0f;
                }
                __syncthreads();
                gemm_tiles(A, k0, col0, w, k0 + 128, 1 << 20, Bs, As, tid);
                __threadfence();
                __syncthreads();
                if (tid == 0) atomicExch(&g_ft[n * 16 + B * 2 + 1], (unsigned)(j + 1));
                gemm_tiles(A, k0, col0, w, k0 + 128 + 128, 128, Bs, As, tid);
                __threadfence();
                __syncthreads();
                if (tid == 0) atomicExch(&g_progh[n * 16 + B * 2 + 1], (unsigned)(j + 1));
            }
        }
    }
    else if (cta >= NBATCH && cta < 24) {
        int n = (cta - NBATCH) / 3;
        int p = 1 + (cta - NBATCH) % 3;
        float* A = g_A + n * MM * SRIDE;
        float* sU    = smdyn;
        float* sdinv = smdyn + 4352;
        float* Bs    = smdyn + 4416;
        float* As    = smdyn + 8512;

        for (int j = 0; j < 5; ++j) {
            int k0 = 64 * j;
            int col0 = 64 * (j + 1);
            int w = NCOL - col0; if (w > 64) w = 64;

            if (tid == 0) { while (ldv(&g_factpub[n]) < (unsigned)(j + 1)) {} }
            __syncthreads();
            __threadfence();

            for (int idx2 = tid; idx2 < 4096; idx2 += NTH) {
                int r = idx2 >> 6, c = idx2 & 63;
                sU[r * SDS + c] = A[(k0 + r) * SRIDE + k0 + c];
            }
            __syncthreads();
            if (tid < 64) sdinv[tid] = __fdividef(1.0f, sU[tid * SDS + tid]);
            if (j >= 2) {
                if (tid == 0) {
                    while (ldv(&g_progh[n * 16 + j * 2 + 0]) < (unsigned)(j - 1)) {}
                    while (ldv(&g_progh[n * 16 + j * 2 + 1]) < (unsigned)(j - 1)) {}
                }
            }
            __syncthreads();
            __threadfence();

            for (int t = j + 2; t <= 6; ++t) {
                if ((t % 3) != p - 1) continue;
                int tr0 = 64 * t;
                int nr = MM - tr0; if (nr > 64) nr = 64;
                l21_rows(A, k0, tr0, nr, sU, sdinv, (float*)0, tid);
                __syncthreads();
            }
            __threadfence();
            __syncthreads();
            if (tid == 0) atomicExch(&g_l21par[n * 3 + (p - 1)], (unsigned)(j + 1));

            if (tid == 0) { while (ldv(&g_uready[n]) < (unsigned)(j + 1)) {} }
            __syncthreads();
            __threadfence();
            for (int idx2 = tid; idx2 < 4096; idx2 += NTH) {
                int r = idx2 >> 6, c = idx2 & 63;
                Bs[idx2] = (c < w) ? A[(k0 + r) * SRIDE + col0 + c] : 0.0f;
            }
            __syncthreads();
            if (tid == 0) {
                while (ldv(&g_progh[n * 16 + (j + 1) * 2 + 0]) < (unsigned)j) {}
                while (ldv(&g_progh[n * 16 + (j + 1) * 2 + 1]) < (unsigned)j) {}
            }
            __syncthreads();
            __threadfence();

            for (int t = j + 2; t <= 6; ++t) {
                if ((t % 3) != p - 1) continue;
                gemm_tiles(A, k0, col0, w, 64 * t, 1 << 20, Bs, As, tid);
                __threadfence();
                __syncthreads();
                if (tid == 0) atomicExch(&g_tdone[n * 8 + t], (unsigned)(j + 1));
            }
        }
    }
    else if (cta < NBATCH) {
        int n = cta;
        float* A = g_A + n * MM * SRIDE;

        float* sT    = smdyn;
        float* sdinv = smdyn + 4352;
        float* Bs    = smdyn + 4416;
        float* As    = smdyn + 8512;

        if (tid == 0) { while (ldv(&g_buildcnt[n]) < 24u) {} }
        __syncthreads();
        __threadfence();

        for (int idx2 = tid; idx2 < 4096; idx2 += NTH)
            sT[(idx2 >> 6) * SDS + (idx2 & 63)] = A[(idx2 >> 6) * SRIDE + (idx2 & 63)];
        __syncthreads();

        for (int k = 0; k < 7; ++k) {
            int k0 = 64 * k;

            if (k < 6) {
                #pragma unroll 1
                for (int g = 0; g < 4; ++g) {
                    int c0 = g * 16;
                    if (wid == 0 && lane < 16) {
                        float x[16];
                        #pragma unroll
                        for (int q = 0; q < 16; ++q) x[q] = sT[(c0 + lane) * SDS + c0 + q];
                        #pragma unroll
                        for (int j = 0; j < 16; ++j) {
                            float piv[16];
                            #pragma unroll
                            for (int q = 0; q < 16; ++q)
                                piv[q] = __shfl_sync(0x0000FFFFu, x[q], j);
                            if (lane > j) {
                                float m = x[j] * __fdividef(1.0f, piv[j]);
                                x[j] = m;
                                #pragma unroll
                                for (int q = 0; q < 16; ++q)
                                    if (q > j) x[q] = fmaf(-m, piv[q], x[q]);
                            }
                        }
                        #pragma unroll
                        for (int q = 0; q < 16; ++q) sT[(c0 + lane) * SDS + c0 + q] = x[q];
                    }
                    __syncthreads();

                    int ntrail = 64 - (c0 + 16);
                    if (tid < ntrail) {
                        int c = c0 + 16 + tid;
                        float x[16];
                        #pragma unroll
                        for (int r = 0; r < 16; ++r) x[r] = sT[(c0 + r) * SDS + c];
                        #pragma unroll
                        for (int i = 0; i < 16; ++i) {
                            float xi = x[i];
                            #pragma unroll
                            for (int r = 0; r < 16; ++r)
                                if (r > i) x[r] = fmaf(-sT[(c0 + r) * SDS + c0 + i], xi, x[r]);
                        }
                        #pragma unroll
                        for (int r = 1; r < 16; ++r) sT[(c0 + r) * SDS + c] = x[r];
                    } else if (tid >= 64 && tid < 64 + ntrail) {
                        int r = c0 + 16 + (tid - 64);
                        float x[16];
                        #pragma unroll
                        for (int q = 0; q < 16; ++q) x[q] = sT[r * SDS + c0 + q];
                        #pragma unroll
                        for (int i = 0; i < 16; ++i) {
                            float xi = x[i] * __fdividef(1.0f, sT[(c0 + i) * SDS + c0 + i]);
                            x[i] = xi;
                            #pragma unroll
                            for (int q = 0; q < 16; ++q)
                                if (q > i) x[q] = fmaf(-xi, sT[(c0 + i) * SDS + c0 + q], x[q]);
                        }
                        #pragma unroll
                        for (int q = 0; q < 16; ++q) sT[r * SDS + c0 + q] = x[q];
                    }
                    __syncthreads();

                    if (ntrail > 0) {
                        int tot = ntrail * ntrail;
                        for (int idx2 = tid; idx2 < tot; idx2 += NTH) {
                            int r = c0 + 16 + idx2 / ntrail;
                            int c = c0 + 16 + idx2 % ntrail;
                            float acc = sT[r * SDS + c];
                            #pragma unroll
                            for (int i = 0; i < 16; ++i)
                                acc = fmaf(-sT[r * SDS + c0 + i], sT[(c0 + i) * SDS + c], acc);
                            sT[r * SDS + c] = acc;
                        }
                        __syncthreads();
                    }
                }
                if (tid < 64) sdinv[tid] = __fdividef(1.0f, sT[tid * SDS + tid]);
                for (int idx2 = tid; idx2 < 4096; idx2 += NTH) {
                    int r = idx2 >> 6, c = idx2 & 63;
                    A[(k0 + r) * SRIDE + k0 + c] = sT[r * SDS + c];
                }
                __threadfence();
                __syncthreads();
                if (tid == 0) atomicExch(&g_factpub[n], (unsigned)(k + 1));
            } else {
                int nbr = 19, nbc = 21;
                int r = tid & 63, cg = tid >> 6;
                for (int j = 0; j < nbr - 1; ++j) {
                    float pinv = __fdividef(1.0f, sT[j * SDS + j]);
                    if (r > j && r < nbr && cg == 0)
                        sT[r * SDS + j] = sT[r * SDS + j] * pinv;
                    __syncthreads();
                    if (r > j && r < nbr) {
                        float m = sT[r * SDS + j];
                        for (int c = j + 1 + cg; c < nbc; c += 8)
                            sT[r * SDS + c] = fmaf(-m, sT[j * SDS + c], sT[r * SDS + c]);
                    }
                    __syncthreads();
                }
                for (int idx2 = tid; idx2 < nbr * nbc; idx2 += NTH) {
                    int rr = idx2 / nbc, cc = idx2 - rr * nbc;
                    A[(k0 + rr) * SRIDE + k0 + cc] = sT[rr * SDS + cc];
                }
                __threadfence();
                __syncthreads();
                if (tid == 0) atomicExch(&g_factpub[n], 7u);
                break;
            }

            int col0 = 64 * (k + 1);
            int w = NCOL - col0; if (w > 64) w = 64;
            int tr0 = col0;
            int nr = MM - tr0; if (nr > 64) nr = 64;

            if (k >= 1) {
                if (tid == 0) { while (ldv(&g_ft[n * 16 + (k + 1) * 2 + 0]) < (unsigned)k) {} }
                __syncthreads();
                __threadfence();
            }

            for (int idx2 = tid; idx2 < 4096; idx2 += NTH) {
                int r = idx2 >> 6, c = idx2 & 63;
                Bs[idx2] = (c < w) ? A[(k0 + r) * SRIDE + col0 + c] : 0.0f;
            }
            __syncthreads();
            trisolve_block(sT, SDS, Bs, tid);
            for (int idx2 = tid; idx2 < 4096; idx2 += NTH) {
                int r = idx2 >> 6, c = idx2 & 63;
                if (c < w) A[(k0 + r) * SRIDE + col0 + c] = Bs[idx2];
            }
            __threadfence();
            __syncthreads();
            if (tid == 0) atomicExch(&g_uready[n], (unsigned)(k + 1));

            if (k >= 1) {
                if (tid == 0) { while (ldv(&g_tdone[n * 8 + (k + 1)]) < (unsigned)k) {} }
                __syncthreads();
                __threadfence();
            }

            l21_rows(A, k0, tr0, nr, sT, sdinv, As, tid);
            __threadfence();
            __syncthreads();
            if (tid == 0) atomicExch(&g_l21pan[n], (unsigned)(k + 1));

            if (k >= 1) {
                if (tid == 0) { while (ldv(&g_ft[n * 16 + (k + 1) * 2 + 1]) < (unsigned)k) {} }
                __syncthreads();
                __threadfence();
            }

            for (int idx2 = tid; idx2 < 4096; idx2 += NTH) {
                int r = idx2 >> 6, c = idx2 & 63;
                sT[r * SDS + c] = (r < nr && c < w) ? A[(tr0 + r) * SRIDE + col0 + c] : 0.0f;
            }
            __syncthreads();
            {
                int c4 = (tid & 15) * 4;
                int r0 = (tid >> 4) * 2;
                int r1 = r0 + 1;
                float4 acc0 = {0.f,0.f,0.f,0.f};
                float4 acc1 = {0.f,0.f,0.f,0.f};
                #pragma unroll
                for (int kk4 = 0; kk4 < 16; ++kk4) {
                    float4 a0 = *(const float4*)&As[r0 * 64 + kk4 * 4];
                    float4 a1 = *(const float4*)&As[r1 * 64 + kk4 * 4];
                    const float* bb = &Bs[(kk4 * 4) * 64 + c4];
                    float4 b0 = *(const float4*)(bb);
                    float4 b1 = *(const float4*)(bb + 64);
                    float4 b2 = *(const float4*)(bb + 128);
                    float4 b3 = *(const float4*)(bb + 192);
                    ACC4(acc0, a0.x, b0) ACC4(acc0, a0.y, b1) ACC4(acc0, a0.z, b2) ACC4(acc0, a0.w, b3)
                    ACC4(acc1, a1.x, b0) ACC4(acc1, a1.y, b1) ACC4(acc1, a1.z, b2) ACC4(acc1, a1.w, b3)
                }
                if (r0 < nr) {
                    float4 v = *(float4*)&sT[r0 * SDS + c4];
                    v.x -= acc0.x; v.y -= acc0.y; v.z -= acc0.z; v.w -= acc0.w;
                    *(float4*)&sT[r0 * SDS + c4] = v;
                }
                if (r1 < nr) {
                    float4 v = *(float4*)&sT[r1 * SDS + c4];
                    v.x -= acc1.x; v.y -= acc1.y; v.z -= acc1.z; v.w -= acc1.w;
                    *(float4*)&sT[r1 * SDS + c4] = v;
                }
            }
            __syncthreads();
        }

        if (tid == 0) {
            for (int B = 2; B <= 6; ++B) {
                while (ldv(&g_progh[n * 16 + B * 2 + 0]) < (unsigned)(B - 1)) {}
                while (ldv(&g_progh[n * 16 + B * 2 + 1]) < (unsigned)(B - 1)) {}
            }
        }
        __syncthreads();
        __threadfence();

        {
            float* sB  = smdyn;
            float* x0s = smdyn + 4416;
            float* x1s = x0s + MM;

            __syncthreads();
            for (int j = tid; j < MM; j += NTH) {
                x0s[j] = A[j * SRIDE + 403];
                x1s[j] = A[j * SRIDE + 404];
            }
            __syncthreads();

            for (int b = 6; b >= 0; --b) {
                int bk0 = b * 64;
                int bnb = (MM - bk0 < 64) ? (MM - bk0) : 64;

                for (int idx2 = tid; idx2 < bnb * bnb; idx2 += NTH) {
                    int r = idx2 / bnb, cc = idx2 - r * bnb;
                    sB[r * 65 + cc] = A[(bk0 + r) * SRIDE + bk0 + cc];
                }
                __syncthreads();

                if (wid == 0) {
                    for (int k = bnb - 1; k >= 0; --k) {
                        float s0 = 0.f, s1 = 0.f;
                        for (int j = k + 1 + lane; j < bnb; j += 32) {
                            float u = sB[k * 65 + j];
                            s0 = fmaf(u, x0s[bk0 + j], s0);
                            s1 = fmaf(u, x1s[bk0 + j], s1);
                        }
                        #pragma unroll
                        for (int off = 16; off > 0; off >>= 1) {
                            s0 += __shfl_down_sync(0xffffffffu, s0, off);
                            s1 += __shfl_down_sync(0xffffffffu, s1, off);
                        }
                        if (lane == 0) {
                            float d = 1.0f / sB[k * 65 + k];
                            x0s[bk0 + k] = (x0s[bk0 + k] - s0) * d;
                            x1s[bk0 + k] = (x1s[bk0 + k] - s1) * d;
                        }
                        __syncwarp();
                    }
                }
                __syncthreads();

                for (int r = tid; r < bk0; r += NTH) {
                    float s0 = 0.f, s1 = 0.f;
                    const float* Ur = A + r * SRIDE + bk0;
                    #pragma unroll 8
                    for (int j = 0; j < bnb; ++j) {
                        float u = Ur[j];
                        s0 = fmaf(u, x0s[bk0 + j], s0);
                        s1 = fmaf(u, x1s[bk0 + j], s1);
                    }
                    x0s[r] -= s0;
                    x1s[r] -= s1;
                }
                __syncthreads();
            }

            for (int j = tid; j < MM; j += NTH) {
                g_sol[(n * MM + j) * 2 + 0] = x0s[j];
                g_sol[(n * MM + j) * 2 + 1] = x1s[j];
            }
            __threadfence();
            __syncthreads();
            if (tid == 0) atomicExch(&g_solflag[n], 1u);
        }
    }

    // ===== fused eval: all 144 CTAs, 3 px/thread =====
    {
        int n = cta % NBATCH;
        int chunk = cta / NBATCH;
        int pbase = chunk * 1536;

        __syncthreads();
        if (tid == 0) { while (ldv(&g_solflag[n]) == 0u) {} }
        __syncthreads();
        __threadfence();

        float4* s_sw = (float4*)smdyn;
        float*  s_aff = smdyn + 1600;

        for (int k = tid; k < KC; k += NTH) {
            float4 t;
            t.x = g_src[(n * KC + k) * 2 + 0];
            t.y = g_src[(n * KC + k) * 2 + 1];
            t.z = g_sol[(n * MM + k) * 2 + 0] * HALF_LN2;
            t.w = g_sol[(n * MM + k) * 2 + 1] * HALF_LN2;
            s_sw[k] = t;
        }
        if (tid < 6) s_aff[tid] = g_sol[(n * MM + 400) * 2 + tid];
        __syncthreads();

        const float* Wp = g_warp + n * 5 * HW;
        #pragma unroll 1
        for (int pi = 0; pi < 3; ++pi) {
            int p = pbase + pi * NTH + tid;
            float q0x = Wp[p];
            float q0y = Wp[HW + p];
            float dlx = Wp[2 * HW + p];
            float dly = Wp[3 * HW + p];
            float mk  = Wp[4 * HW + p];

            float a0x = 0.f, a0y = 0.f, a1x = 0.f, a1y = 0.f, a2x = 0.f, a2y = 0.f;

            #pragma unroll 4
            for (int k = 0; k < KC; ++k) {
                float4 s = s_sw[k];
                float d0x = q0x - s.x;
                float d0y = q0y - s.y;
                float e0x = fmaf(2.0f, d0x, STEPC);
                float e0y = fmaf(2.0f, d0y, STEPC);
                float r0 = fmaf(d0x, d0x, d0y * d0y) + EPSV;
                float r1 = fmaf(STEPC, e0x, r0);
                float r2 = fmaf(STEPC, e0y, r0);
                float u0 = r0 * __log2f(r0);
                float u1 = r1 * __log2f(r1);
                float u2 = r2 * __log2f(r2);
                a0x = fmaf(u0, s.z, a0x);  a0y = fmaf(u0, s.w, a0y);
                a1x = fmaf(u1, s.z, a1x);  a1y = fmaf(u1, s.w, a1y);
                a2x = fmaf(u2, s.z, a2x);  a2y = fmaf(u2, s.w, a2y);
            }

            float q1x = q0x + STEPC;
            float q2y = q0y + STEPC;
            float c0x = a0x + s_aff[0] + s_aff[2] * q0x + s_aff[4] * q0y;
            float c0y = a0y + s_aff[1] + s_aff[3] * q0x + s_aff[5] * q0y;
            float c1x = a1x + s_aff[0] + s_aff[2] * q1x + s_aff[4] * q0y;
            float c1y = a1y + s_aff[1] + s_aff[3] * q1x + s_aff[5] * q0y;
            float c2x = a2x + s_aff[0] + s_aff[2] * q0x + s_aff[4] * q2y;
            float c2y = a2y + s_aff[1] + s_aff[3] * q0x + s_aff[5] * q2y;

            float ja = (c1x - c0x) / STEPC;
            float jb = (c1y - c0y) / STEPC;
            float jc = (c2x - c0x) / STEPC;
            float jd = (c2y - c0y) / STEPC;

            float dnx = ja * dlx + jc * dly;
            float dny = jb * dlx + jd * dly;

            int i = p / WW;
            int j = p - i * WW;
            float gx = j * STEPC - 1.0f;
            float gy = i * STEPC - 1.0f;
            float dfx = (gx + dnx) * mk - 2.0f * (1.0f - mk);
            float dfy = (gy + dny) * mk - 2.0f * (1.0f - mk);

            outDef[(n * HW + p) * 2 + 0] = dfx;
            outDef[(n * HW + p) * 2 + 1] = dfy;
        }
    }
}

extern "C" void kernel_launch(void* const* d_in, const int* in_sizes, int n_in,
                              void* d_out, int out_size)
{
    const float* a0 = (const float*)d_in[0];
    const float* a1 = (const float*)d_in[1];
    const float* duv;
    const float* uv;
    if (in_sizes[0] == 2 * HW) { duv = a0; uv = a1; }
    else                        { duv = a1; uv = a0; }

    float* out = (float*)d_out;
    float* outDef  = out;
    float* outMask = out + NBATCH * HW * 2;

    const int SMBYTES = 12608 * (int)sizeof(float);
    cudaFuncSetAttribute(solve_kernel,
                         cudaFuncAttributeMaxDynamicSharedMemorySize, SMBYTES);

    warp_kernel<<<(NBATCH * HW + 255) / 256, 256>>>(duv, uv, outMask);
    solve_kernel<<<144, NTH, SMBYTES>>>(outDef);
}